// round 6
// baseline (speedup 1.0000x reference)
#include <cuda_runtime.h>
#include <math.h>
#include <stdint.h>

// Problem constants
#define B_  2
#define S_  2048
#define D_  2048
#define H_  16
#define HD_ 128
#define M_  (B_*S_)   // 4096 rows

// GEMM tiling (tf32 tensor-core path)
#define BM 128
#define BN 128
#define BK 32
#define LDW 36        // BK + 4 pad words
#define GSTAGE (BM * LDW)             // words per stage per operand
#define GSMEM_WORDS (4 * GSTAGE)      // 2 stages x (A,B)

// Flash-attention tiling (tensor-core)
#define FBR 128       // query rows per block
#define FBC 64        // kv rows per tile
#define QLD 132       // pitch (words) for Q/K/V tiles: 128+4  (pitch mod 32 == 4)
#define PLD 68        // pitch (words) for score/prob tile: 64+4

// Scratch (device globals: allocation-free rule)
__device__ float g_q[(size_t)M_ * D_];    // Q in (B,H,S,HD) layout
__device__ float g_ctx[(size_t)M_ * D_];  // attention context in (B,S,D) layout

__device__ __forceinline__ uint32_t f2tf32(float x) {
    uint32_t u;
    asm("cvt.rna.tf32.f32 %0, %1;" : "=r"(u) : "f"(x));
    return u;
}

__device__ __forceinline__ void mma_tf32(float c[4], uint32_t a0, uint32_t a1,
                                         uint32_t a2, uint32_t a3,
                                         uint32_t b0, uint32_t b1) {
    asm volatile(
        "mma.sync.aligned.m16n8k8.row.col.f32.tf32.tf32.f32 "
        "{%0,%1,%2,%3}, {%4,%5,%6,%7}, {%8,%9}, {%0,%1,%2,%3};"
        : "+f"(c[0]), "+f"(c[1]), "+f"(c[2]), "+f"(c[3])
        : "r"(a0), "r"(a1), "r"(a2), "r"(a3), "r"(b0), "r"(b1));
}

// ---------------------------------------------------------------------------
// GEMM (tf32 tensor cores): Y = X @ W^T + bias.
// 2-stage double-buffered smem: one barrier per k-tile, STS overlaps mma.
// ---------------------------------------------------------------------------
__global__ __launch_bounds__(256) void gemm_tf32(const float* __restrict__ X,
                                                 const float* __restrict__ W,
                                                 const float* __restrict__ bias,
                                                 float* __restrict__ Y,
                                                 int reshape)
{
    extern __shared__ uint32_t gsm[];
    uint32_t* As = gsm;                 // [2][BM*LDW]
    uint32_t* Bs = gsm + 2 * GSTAGE;    // [2][BN*LDW]

    const int K    = D_;
    const int tid  = threadIdx.x;
    const int lane = tid & 31;
    const int warp = tid >> 5;
    const int wm   = warp >> 2;
    const int wn   = warp & 3;
    const int lr   = lane >> 2;
    const int lc   = lane & 3;
    const int m0   = blockIdx.y * BM;
    const int n0   = blockIdx.x * BN;

    const int lrow = tid >> 3;
    const int lcol = (tid & 7) << 2;
    const float* Xp = X + (size_t)(m0 + lrow) * K + lcol;
    const float* Wp = W + (size_t)(n0 + lrow) * K + lcol;

    float acc[4][4][4];
#pragma unroll
    for (int i = 0; i < 4; i++)
#pragma unroll
        for (int j = 0; j < 4; j++)
#pragma unroll
            for (int c = 0; c < 4; c++) acc[i][j][c] = 0.f;

    float4 pa[4], pb[4];
    // Preload tile 0 into stage 0.
#pragma unroll
    for (int l = 0; l < 4; l++) {
        pa[l] = *reinterpret_cast<const float4*>(Xp + (size_t)(l * 32) * K);
        pb[l] = *reinterpret_cast<const float4*>(Wp + (size_t)(l * 32) * K);
    }
#pragma unroll
    for (int l = 0; l < 4; l++) {
        uint32_t* a = &As[(lrow + l * 32) * LDW + lcol];
        a[0] = f2tf32(pa[l].x); a[1] = f2tf32(pa[l].y);
        a[2] = f2tf32(pa[l].z); a[3] = f2tf32(pa[l].w);
        uint32_t* b = &Bs[(lrow + l * 32) * LDW + lcol];
        b[0] = f2tf32(pb[l].x); b[1] = f2tf32(pb[l].y);
        b[2] = f2tf32(pb[l].z); b[3] = f2tf32(pb[l].w);
    }
    __syncthreads();

    const int NKT = K / BK;   // 64
    for (int kt = 0; kt < NKT; ++kt) {
        const bool has_next = (kt + 1 < NKT);
        const uint32_t* Ac = &As[(kt & 1) * GSTAGE];
        const uint32_t* Bc = &Bs[(kt & 1) * GSTAGE];
        uint32_t* An = &As[((kt + 1) & 1) * GSTAGE];
        uint32_t* Bn = &Bs[((kt + 1) & 1) * GSTAGE];

        if (has_next) {
            const int ko = (kt + 1) * BK;
#pragma unroll
            for (int l = 0; l < 4; l++) {
                pa[l] = *reinterpret_cast<const float4*>(Xp + (size_t)(l * 32) * K + ko);
                pb[l] = *reinterpret_cast<const float4*>(Wp + (size_t)(l * 32) * K + ko);
            }
        }

        // Compute on current stage (store of next stage interleaves freely).
#pragma unroll
        for (int ks = 0; ks < 4; ++ks) {
            const int k0 = ks * 8;
            uint32_t af[4][4], bf[4][2];
#pragma unroll
            for (int mf = 0; mf < 4; mf++) {
                const int r = wm * 64 + mf * 16 + lr;
                af[mf][0] = Ac[r * LDW + k0 + lc];
                af[mf][1] = Ac[(r + 8) * LDW + k0 + lc];
                af[mf][2] = Ac[r * LDW + k0 + 4 + lc];
                af[mf][3] = Ac[(r + 8) * LDW + k0 + 4 + lc];
            }
#pragma unroll
            for (int nf = 0; nf < 4; nf++) {
                const int n = wn * 32 + nf * 8 + lr;
                bf[nf][0] = Bc[n * LDW + k0 + lc];
                bf[nf][1] = Bc[n * LDW + k0 + 4 + lc];
            }
#pragma unroll
            for (int mf = 0; mf < 4; mf++)
#pragma unroll
                for (int nf = 0; nf < 4; nf++)
                    mma_tf32(acc[mf][nf], af[mf][0], af[mf][1], af[mf][2], af[mf][3],
                             bf[nf][0], bf[nf][1]);
        }

        if (has_next) {
#pragma unroll
            for (int l = 0; l < 4; l++) {
                uint32_t* a = &An[(lrow + l * 32) * LDW + lcol];
                a[0] = f2tf32(pa[l].x); a[1] = f2tf32(pa[l].y);
                a[2] = f2tf32(pa[l].z); a[3] = f2tf32(pa[l].w);
                uint32_t* b = &Bn[(lrow + l * 32) * LDW + lcol];
                b[0] = f2tf32(pb[l].x); b[1] = f2tf32(pb[l].y);
                b[2] = f2tf32(pb[l].z); b[3] = f2tf32(pb[l].w);
            }
        }
        __syncthreads();
    }

    const int hh = n0 >> 7;
#pragma unroll
    for (int mf = 0; mf < 4; mf++) {
#pragma unroll
        for (int nf = 0; nf < 4; nf++) {
            const int nloc = wn * 32 + nf * 8 + lc * 2;
            const int n    = n0 + nloc;
            const float b0 = bias[n];
            const float b1 = bias[n + 1];
#pragma unroll
            for (int half = 0; half < 2; half++) {
                const int m = m0 + wm * 64 + mf * 16 + lr + half * 8;
                const float v0 = acc[mf][nf][half * 2 + 0] + b0;
                const float v1 = acc[mf][nf][half * 2 + 1] + b1;
                size_t idx;
                if (reshape) {
                    const int bb = m >> 11;
                    const int ss = m & (S_ - 1);
                    const int hd = n & (HD_ - 1);
                    idx = (((size_t)(bb * H_ + hh)) * S_ + ss) * HD_ + hd;
                } else {
                    idx = (size_t)m * D_ + n;
                }
                *reinterpret_cast<float2*>(Y + idx) = make_float2(v0, v1);
            }
        }
    }
}

// ---------------------------------------------------------------------------
// Causal flash attention, tf32 tensor cores.
// Softmax: all 256 threads, 2 per row (halves joined by shfl), skewed
// column order for near-conflict-free smem row scans.
// ---------------------------------------------------------------------------
__global__ __launch_bounds__(256) void flash_tc(const float* __restrict__ Qg,
                                                const float* __restrict__ Kg,
                                                const float* __restrict__ Vg,
                                                float* __restrict__ ctx)
{
    extern __shared__ uint32_t smu[];
    uint32_t* Qs = smu;                       // [FBR][QLD] tf32
    uint32_t* Ks = Qs + FBR * QLD;            // [FBC][QLD] tf32
    uint32_t* Vs = Ks + FBC * QLD;            // [FBC][QLD] tf32
    float*    Ps = (float*)(Vs + FBC * QLD);  // [FBR][PLD] scores fp32 / probs tf32-bits
    float*    mrow = Ps + FBR * PLD;          // [FBR]
    float*    lrow = mrow + FBR;
    float*    arow = lrow + FBR;

    const int bh  = blockIdx.y;
    const int qt  = (int)gridDim.x - 1 - (int)blockIdx.x;   // heavy blocks first
    const int q0  = qt * FBR;
    const int tid = threadIdx.x;
    const int lane = tid & 31;
    const int warp = tid >> 5;
    const int wm = warp >> 1;      // 0..3 -> 32-row slab
    const int wn = warp & 1;       // 0..1
    const int lr = lane >> 2;      // 0..7
    const int lc = lane & 3;       // 0..3

    const float* Qb = Qg + ((size_t)bh * S_ + q0) * HD_;
    const float* Kb = Kg + (size_t)bh * S_ * HD_;
    const float* Vb = Vg + (size_t)bh * S_ * HD_;

    // Load Q tile (128x128) as tf32.
#pragma unroll
    for (int l = 0; l < 16; ++l) {
        int f   = tid + l * 256;
        int row = f >> 5;
        int c4  = (f & 31) << 2;
        float4 v = *reinterpret_cast<const float4*>(Qb + (size_t)row * HD_ + c4);
        *reinterpret_cast<uint4*>(&Qs[row * QLD + c4]) =
            make_uint4(f2tf32(v.x), f2tf32(v.y), f2tf32(v.z), f2tf32(v.w));
    }
    if (tid < FBR) { mrow[tid] = -1e30f; lrow[tid] = 0.f; }

    // O accumulator: warp tile 32(m) x 64(n) = 2 x 8 frags.
    float o[2][8][4];
#pragma unroll
    for (int i = 0; i < 2; i++)
#pragma unroll
        for (int j = 0; j < 8; j++)
#pragma unroll
            for (int c = 0; c < 4; c++) o[i][j][c] = 0.f;

    const float scale = 0.08838834764831845f;  // 1/sqrt(128)

    // Softmax role: 2 threads per row.
    const int srow_i = tid >> 1;         // 0..127
    const int shalf  = tid & 1;          // 0..1
    const int sskew  = srow_i & 31;

    const int ntiles = 2 * qt + 2;
    for (int t = 0; t < ntiles; ++t) {
        const int k0 = t * FBC;
        __syncthreads();   // prior readers of Ks/Vs/Ps done

        // Load K,V tiles (64x128 each) as tf32.
#pragma unroll
        for (int l = 0; l < 8; ++l) {
            int f   = tid + l * 256;
            int row = f >> 5;
            int c4  = (f & 31) << 2;
            float4 kv = *reinterpret_cast<const float4*>(Kb + (size_t)(k0 + row) * HD_ + c4);
            *reinterpret_cast<uint4*>(&Ks[row * QLD + c4]) =
                make_uint4(f2tf32(kv.x), f2tf32(kv.y), f2tf32(kv.z), f2tf32(kv.w));
            float4 vv = *reinterpret_cast<const float4*>(Vb + (size_t)(k0 + row) * HD_ + c4);
            *reinterpret_cast<uint4*>(&Vs[row * QLD + c4]) =
                make_uint4(f2tf32(vv.x), f2tf32(vv.y), f2tf32(vv.z), f2tf32(vv.w));
        }
        __syncthreads();

        // S = Q @ K^T : warp tile 32x32, frags 2(m16) x 4(n8), K-dim 128.
        float sacc[2][4][4];
#pragma unroll
        for (int i = 0; i < 2; i++)
#pragma unroll
            for (int j = 0; j < 4; j++)
#pragma unroll
                for (int c = 0; c < 4; c++) sacc[i][j][c] = 0.f;

#pragma unroll
        for (int ks = 0; ks < 16; ++ks) {
            const int k = ks * 8;
            uint32_t af[2][4], bf[4][2];
#pragma unroll
            for (int mf = 0; mf < 2; mf++) {
                const int r = wm * 32 + mf * 16 + lr;
                af[mf][0] = Qs[r * QLD + k + lc];
                af[mf][1] = Qs[(r + 8) * QLD + k + lc];
                af[mf][2] = Qs[r * QLD + k + 4 + lc];
                af[mf][3] = Qs[(r + 8) * QLD + k + 4 + lc];
            }
#pragma unroll
            for (int nf = 0; nf < 4; nf++) {
                const int n = wn * 32 + nf * 8 + lr;
                bf[nf][0] = Ks[n * QLD + k + lc];
                bf[nf][1] = Ks[n * QLD + k + 4 + lc];
            }
#pragma unroll
            for (int mf = 0; mf < 2; mf++)
#pragma unroll
                for (int nf = 0; nf < 4; nf++)
                    mma_tf32(sacc[mf][nf], af[mf][0], af[mf][1], af[mf][2], af[mf][3],
                             bf[nf][0], bf[nf][1]);
        }

        // Scale (+ causal mask on diagonal tiles), stash scores in Ps.
        const bool needmask = (k0 + FBC - 1 > q0);   // only last two tiles
#pragma unroll
        for (int mf = 0; mf < 2; mf++) {
#pragma unroll
            for (int nf = 0; nf < 4; nf++) {
#pragma unroll
                for (int c = 0; c < 4; c++) {
                    const int rloc = wm * 32 + mf * 16 + lr + (c >> 1) * 8;
                    const int cloc = wn * 32 + nf * 8 + lc * 2 + (c & 1);
                    float v = sacc[mf][nf][c] * scale;
                    if (needmask && (k0 + cloc) > (q0 + rloc)) v = -1e9f;
                    Ps[rloc * PLD + cloc] = v;
                }
            }
        }
        __syncthreads();

        // Online softmax: 2 threads per row (adjacent lanes), skewed scan.
        {
            float* srow = Ps + srow_i * PLD + shalf * 32;
            uint32_t* prow = (uint32_t*)srow;
            float tm = -1e30f;
#pragma unroll 8
            for (int j = 0; j < 32; ++j) {
                const int jj = (j + sskew) & 31;
                tm = fmaxf(tm, srow[jj]);
            }
            tm = fmaxf(tm, __shfl_xor_sync(0xffffffffu, tm, 1));
            const float mo = mrow[srow_i];
            const float mn = fmaxf(mo, tm);
            const float al = __expf(mo - mn);
            float sum = 0.f;
#pragma unroll 8
            for (int j = 0; j < 32; ++j) {
                const int jj = (j + sskew) & 31;
                const float p = __expf(srow[jj] - mn);
                sum += p;
                prow[jj] = f2tf32(p);
            }
            sum += __shfl_xor_sync(0xffffffffu, sum, 1);
            if (shalf == 0) {
                lrow[srow_i] = lrow[srow_i] * al + sum;
                mrow[srow_i] = mn;
                arow[srow_i] = al;
            }
        }
        __syncthreads();

        // Rescale O by alpha, then O += P @ V.
        {
            float al0 = arow[wm * 32 + lr];
            float al1 = arow[wm * 32 + lr + 8];
            float al2 = arow[wm * 32 + 16 + lr];
            float al3 = arow[wm * 32 + 16 + lr + 8];
#pragma unroll
            for (int nf = 0; nf < 8; nf++) {
                o[0][nf][0] *= al0; o[0][nf][1] *= al0;
                o[0][nf][2] *= al1; o[0][nf][3] *= al1;
                o[1][nf][0] *= al2; o[1][nf][1] *= al2;
                o[1][nf][2] *= al3; o[1][nf][3] *= al3;
            }
        }

        const uint32_t* Pb = (const uint32_t*)Ps;
#pragma unroll
        for (int ks = 0; ks < 8; ++ks) {
            const int k = ks * 8;
            uint32_t af[2][4], bf[8][2];
#pragma unroll
            for (int mf = 0; mf < 2; mf++) {
                const int r = wm * 32 + mf * 16 + lr;
                af[mf][0] = Pb[r * PLD + k + lc];
                af[mf][1] = Pb[(r + 8) * PLD + k + lc];
                af[mf][2] = Pb[r * PLD + k + 4 + lc];
                af[mf][3] = Pb[(r + 8) * PLD + k + 4 + lc];
            }
#pragma unroll
            for (int nf = 0; nf < 8; nf++) {
                const int n = wn * 64 + nf * 8 + lr;
                bf[nf][0] = Vs[(k + lc) * QLD + n];
                bf[nf][1] = Vs[(k + 4 + lc) * QLD + n];
            }
#pragma unroll
            for (int mf = 0; mf < 2; mf++)
#pragma unroll
                for (int nf = 0; nf < 8; nf++)
                    mma_tf32(o[mf][nf], af[mf][0], af[mf][1], af[mf][2], af[mf][3],
                             bf[nf][0], bf[nf][1]);
        }
    }

    __syncthreads();

    // Epilogue: normalize rows by 1/l and write ctx in (B,S,D).
    const int bb = bh / H_;
    const int hh = bh % H_;
#pragma unroll
    for (int mf = 0; mf < 2; mf++) {
#pragma unroll
        for (int half = 0; half < 2; half++) {
            const int rloc = wm * 32 + mf * 16 + lr + half * 8;
            const float inv = 1.0f / lrow[rloc];
            float* dst = ctx + ((size_t)bb * S_ + q0 + rloc) * D_ + hh * HD_;
#pragma unroll
            for (int nf = 0; nf < 8; nf++) {
                const int cloc = wn * 64 + nf * 8 + lc * 2;
                *reinterpret_cast<float2*>(dst + cloc) =
                    make_float2(o[mf][nf][half * 2 + 0] * inv,
                                o[mf][nf][half * 2 + 1] * inv);
            }
        }
    }
}

// ---------------------------------------------------------------------------
// kernel_launch
// ---------------------------------------------------------------------------
extern "C" void kernel_launch(void* const* d_in, const int* in_sizes, int n_in,
                              void* d_out, int out_size)
{
    const float* X  = (const float*)d_in[0];
    const float* Wq = (const float*)d_in[2];
    const float* bq = (const float*)d_in[3];
    const float* Wk = (const float*)d_in[4];
    const float* bk = (const float*)d_in[5];
    const float* Wv = (const float*)d_in[6];
    const float* bv = (const float*)d_in[7];
    const float* Wo = (const float*)d_in[8];
    const float* bo = (const float*)d_in[9];

    float* out = (float*)d_out;
    const size_t OFF = (size_t)B_ * S_ * D_;
    float* kout = out + OFF;
    float* vout = out + 2 * OFF;

    static float* qbuf = nullptr;
    static float* cbuf = nullptr;
    static const int FSMEM = (FBR * QLD + 2 * FBC * QLD + FBR * PLD + 3 * FBR) * (int)sizeof(uint32_t);
    static const int GSMEM = GSMEM_WORDS * (int)sizeof(uint32_t);
    if (qbuf == nullptr) {
        cudaGetSymbolAddress((void**)&qbuf, g_q);
        cudaGetSymbolAddress((void**)&cbuf, g_ctx);
        cudaFuncSetAttribute(flash_tc, cudaFuncAttributeMaxDynamicSharedMemorySize, FSMEM);
        cudaFuncSetAttribute(gemm_tf32, cudaFuncAttributeMaxDynamicSharedMemorySize, GSMEM);
    }

    dim3 gg(D_ / BN, M_ / BM);   // (16, 32)
    gemm_tf32<<<gg, 256, GSMEM>>>(X, Wq, bq, qbuf, 1);
    gemm_tf32<<<gg, 256, GSMEM>>>(X, Wk, bk, kout, 1);
    gemm_tf32<<<gg, 256, GSMEM>>>(X, Wv, bv, vout, 1);

    flash_tc<<<dim3(S_ / FBR, B_ * H_), 256, FSMEM>>>(qbuf, kout, vout, cbuf);

    gemm_tf32<<<gg, 256, GSMEM>>>(cbuf, Wo, bo, out, 0);
}

// round 7
// speedup vs baseline: 1.1028x; 1.1028x over previous
#include <cuda_runtime.h>
#include <math.h>
#include <stdint.h>

// Problem constants
#define B_  2
#define S_  2048
#define D_  2048
#define H_  16
#define HD_ 128
#define M_  (B_*S_)   // 4096 rows

// GEMM tiling (tf32 tensor-core path)
#define BM 128
#define BN 128
#define BK 32
#define LDW 36        // BK + 4 pad words

// Flash-attention tiling (tensor-core)
#define FBR 128       // query rows per block
#define FBC 64        // kv rows per tile
#define QLD 132       // pitch (words) for Q/K/V tiles: 128+4  (pitch mod 32 == 4)

// Scratch (device globals: allocation-free rule)
__device__ float g_q[(size_t)M_ * D_];    // Q in (B,H,S,HD) layout
__device__ float g_ctx[(size_t)M_ * D_];  // attention context in (B,S,D) layout

__device__ __forceinline__ uint32_t f2tf32(float x) {
    uint32_t u;
    asm("cvt.rna.tf32.f32 %0, %1;" : "=r"(u) : "f"(x));
    return u;
}

__device__ __forceinline__ void mma_tf32(float c[4], uint32_t a0, uint32_t a1,
                                         uint32_t a2, uint32_t a3,
                                         uint32_t b0, uint32_t b1) {
    asm volatile(
        "mma.sync.aligned.m16n8k8.row.col.f32.tf32.tf32.f32 "
        "{%0,%1,%2,%3}, {%4,%5,%6,%7}, {%8,%9}, {%0,%1,%2,%3};"
        : "+f"(c[0]), "+f"(c[1]), "+f"(c[2]), "+f"(c[3])
        : "r"(a0), "r"(a1), "r"(a2), "r"(a3), "r"(b0), "r"(b1));
}

// ---------------------------------------------------------------------------
// GEMM (tf32 tensor cores): Y = X @ W^T + bias.  (round-5 version, reverted)
// ---------------------------------------------------------------------------
__global__ __launch_bounds__(256) void gemm_tf32(const float* __restrict__ X,
                                                 const float* __restrict__ W,
                                                 const float* __restrict__ bias,
                                                 float* __restrict__ Y,
                                                 int reshape)
{
    __shared__ uint32_t As[BM * LDW];
    __shared__ uint32_t Bs[BN * LDW];

    const int K    = D_;
    const int tid  = threadIdx.x;
    const int lane = tid & 31;
    const int warp = tid >> 5;
    const int wm   = warp >> 2;
    const int wn   = warp & 3;
    const int lr   = lane >> 2;
    const int lc   = lane & 3;
    const int m0   = blockIdx.y * BM;
    const int n0   = blockIdx.x * BN;

    const int lrow = tid >> 3;
    const int lcol = (tid & 7) << 2;
    const float* Xp = X + (size_t)(m0 + lrow) * K + lcol;
    const float* Wp = W + (size_t)(n0 + lrow) * K + lcol;

    float acc[4][4][4];
#pragma unroll
    for (int i = 0; i < 4; i++)
#pragma unroll
        for (int j = 0; j < 4; j++)
#pragma unroll
            for (int c = 0; c < 4; c++) acc[i][j][c] = 0.f;

    float4 pa[4], pb[4];
#pragma unroll
    for (int l = 0; l < 4; l++) {
        pa[l] = *reinterpret_cast<const float4*>(Xp + (size_t)(l * 32) * K);
        pb[l] = *reinterpret_cast<const float4*>(Wp + (size_t)(l * 32) * K);
    }
#pragma unroll
    for (int l = 0; l < 4; l++) {
        uint32_t* a = &As[(lrow + l * 32) * LDW + lcol];
        a[0] = f2tf32(pa[l].x); a[1] = f2tf32(pa[l].y);
        a[2] = f2tf32(pa[l].z); a[3] = f2tf32(pa[l].w);
        uint32_t* b = &Bs[(lrow + l * 32) * LDW + lcol];
        b[0] = f2tf32(pb[l].x); b[1] = f2tf32(pb[l].y);
        b[2] = f2tf32(pb[l].z); b[3] = f2tf32(pb[l].w);
    }
    __syncthreads();

    const int NKT = K / BK;
    for (int kt = 0; kt < NKT; ++kt) {
        const bool has_next = (kt + 1 < NKT);
        if (has_next) {
            const int ko = (kt + 1) * BK;
#pragma unroll
            for (int l = 0; l < 4; l++) {
                pa[l] = *reinterpret_cast<const float4*>(Xp + (size_t)(l * 32) * K + ko);
                pb[l] = *reinterpret_cast<const float4*>(Wp + (size_t)(l * 32) * K + ko);
            }
        }
#pragma unroll
        for (int ks = 0; ks < 4; ++ks) {
            const int k0 = ks * 8;
            uint32_t af[4][4], bf[4][2];
#pragma unroll
            for (int mf = 0; mf < 4; mf++) {
                const int r = wm * 64 + mf * 16 + lr;
                af[mf][0] = As[r * LDW + k0 + lc];
                af[mf][1] = As[(r + 8) * LDW + k0 + lc];
                af[mf][2] = As[r * LDW + k0 + 4 + lc];
                af[mf][3] = As[(r + 8) * LDW + k0 + 4 + lc];
            }
#pragma unroll
            for (int nf = 0; nf < 4; nf++) {
                const int n = wn * 32 + nf * 8 + lr;
                bf[nf][0] = Bs[n * LDW + k0 + lc];
                bf[nf][1] = Bs[n * LDW + k0 + 4 + lc];
            }
#pragma unroll
            for (int mf = 0; mf < 4; mf++)
#pragma unroll
                for (int nf = 0; nf < 4; nf++)
                    mma_tf32(acc[mf][nf], af[mf][0], af[mf][1], af[mf][2], af[mf][3],
                             bf[nf][0], bf[nf][1]);
        }
        __syncthreads();
        if (has_next) {
#pragma unroll
            for (int l = 0; l < 4; l++) {
                uint32_t* a = &As[(lrow + l * 32) * LDW + lcol];
                a[0] = f2tf32(pa[l].x); a[1] = f2tf32(pa[l].y);
                a[2] = f2tf32(pa[l].z); a[3] = f2tf32(pa[l].w);
                uint32_t* b = &Bs[(lrow + l * 32) * LDW + lcol];
                b[0] = f2tf32(pb[l].x); b[1] = f2tf32(pb[l].y);
                b[2] = f2tf32(pb[l].z); b[3] = f2tf32(pb[l].w);
            }
            __syncthreads();
        }
    }

    const int hh = n0 >> 7;
#pragma unroll
    for (int mf = 0; mf < 4; mf++) {
#pragma unroll
        for (int nf = 0; nf < 4; nf++) {
            const int nloc = wn * 32 + nf * 8 + lc * 2;
            const int n    = n0 + nloc;
            const float b0 = bias[n];
            const float b1 = bias[n + 1];
#pragma unroll
            for (int half = 0; half < 2; half++) {
                const int m = m0 + wm * 64 + mf * 16 + lr + half * 8;
                const float v0 = acc[mf][nf][half * 2 + 0] + b0;
                const float v1 = acc[mf][nf][half * 2 + 1] + b1;
                size_t idx;
                if (reshape) {
                    const int bb = m >> 11;
                    const int ss = m & (S_ - 1);
                    const int hd = n & (HD_ - 1);
                    idx = (((size_t)(bb * H_ + hh)) * S_ + ss) * HD_ + hd;
                } else {
                    idx = (size_t)m * D_ + n;
                }
                *reinterpret_cast<float2*>(Y + idx) = make_float2(v0, v1);
            }
        }
    }
}

// ---------------------------------------------------------------------------
// Causal flash attention, tf32 tensor cores, FA2-style register-resident P.
// 8 warps; warp w owns query rows [16w, 16w+16).  QK^T: 1x8 frags (m16 x n64).
// Softmax entirely in registers (quad shfl reductions).  PV A-fragments built
// from S-fragment registers via shfl (no P smem, no softmax barriers).
// 2 __syncthreads per kv tile (K/V smem reuse only).
// ---------------------------------------------------------------------------
__global__ __launch_bounds__(256) void flash_tc(const float* __restrict__ Qg,
                                                const float* __restrict__ Kg,
                                                const float* __restrict__ Vg,
                                                float* __restrict__ ctx)
{
    extern __shared__ uint32_t smu[];
    uint32_t* Qs = smu;                       // [FBR][QLD] tf32
    uint32_t* Ks = Qs + FBR * QLD;            // [FBC][QLD] tf32
    uint32_t* Vs = Ks + FBC * QLD;            // [FBC][QLD] tf32

    const int bh  = blockIdx.y;
    const int qt  = (int)gridDim.x - 1 - (int)blockIdx.x;   // heavy blocks first
    const int q0  = qt * FBR;
    const int tid = threadIdx.x;
    const int lane = tid & 31;
    const int warp = tid >> 5;
    const int lr = lane >> 2;      // 0..7
    const int lc = lane & 3;       // 0..3
    const int wrow = warp * 16;    // warp's first query row (local)

    const float* Qb = Qg + ((size_t)bh * S_ + q0) * HD_;
    const float* Kb = Kg + (size_t)bh * S_ * HD_;
    const float* Vb = Vg + (size_t)bh * S_ * HD_;

    // Load Q tile (128x128) as tf32.
#pragma unroll
    for (int l = 0; l < 16; ++l) {
        int f   = tid + l * 256;
        int row = f >> 5;
        int c4  = (f & 31) << 2;
        float4 v = *reinterpret_cast<const float4*>(Qb + (size_t)row * HD_ + c4);
        *reinterpret_cast<uint4*>(&Qs[row * QLD + c4]) =
            make_uint4(f2tf32(v.x), f2tf32(v.y), f2tf32(v.z), f2tf32(v.w));
    }

    // O accumulator: warp tile 16(m) x 128(n) = 16 n-frags.
    float o[16][4];
#pragma unroll
    for (int j = 0; j < 16; j++)
#pragma unroll
        for (int c = 0; c < 4; c++) o[j][c] = 0.f;

    // Per-thread softmax state: rows (wrow+lr) and (wrow+lr+8), quad-replicated.
    float m0 = -1e30f, m1 = -1e30f, l0 = 0.f, l1 = 0.f;

    const float scale = 0.08838834764831845f;  // 1/sqrt(128)
    const unsigned FULL = 0xffffffffu;
    const int srcA = (lane & 28) | (lc >> 1);  // quad lane holding cols {lc&~1, lc|1}
    const int srcB = srcA + 2;                 // quad lane holding cols {4+..}

    const int ntiles = 2 * qt + 2;
    for (int t = 0; t < ntiles; ++t) {
        const int k0 = t * FBC;
        __syncthreads();   // prior PV readers of Ks/Vs done

        // Load K,V tiles (64x128 each) as tf32.
#pragma unroll
        for (int l = 0; l < 8; ++l) {
            int f   = tid + l * 256;
            int row = f >> 5;
            int c4  = (f & 31) << 2;
            float4 kv = *reinterpret_cast<const float4*>(Kb + (size_t)(k0 + row) * HD_ + c4);
            *reinterpret_cast<uint4*>(&Ks[row * QLD + c4]) =
                make_uint4(f2tf32(kv.x), f2tf32(kv.y), f2tf32(kv.z), f2tf32(kv.w));
            float4 vv = *reinterpret_cast<const float4*>(Vb + (size_t)(k0 + row) * HD_ + c4);
            *reinterpret_cast<uint4*>(&Vs[row * QLD + c4]) =
                make_uint4(f2tf32(vv.x), f2tf32(vv.y), f2tf32(vv.z), f2tf32(vv.w));
        }
        __syncthreads();

        // S = Q @ K^T : warp tile 16x64 -> 8 n-frags, K-dim 128.
        float sacc[8][4];
#pragma unroll
        for (int j = 0; j < 8; j++)
#pragma unroll
            for (int c = 0; c < 4; c++) sacc[j][c] = 0.f;

#pragma unroll
        for (int ks = 0; ks < 16; ++ks) {
            const int k = ks * 8;
            uint32_t a0 = Qs[(wrow + lr) * QLD + k + lc];
            uint32_t a1 = Qs[(wrow + lr + 8) * QLD + k + lc];
            uint32_t a2 = Qs[(wrow + lr) * QLD + k + 4 + lc];
            uint32_t a3 = Qs[(wrow + lr + 8) * QLD + k + 4 + lc];
#pragma unroll
            for (int nf = 0; nf < 8; nf++) {
                const int n = nf * 8 + lr;
                uint32_t b0 = Ks[n * QLD + k + lc];
                uint32_t b1 = Ks[n * QLD + k + 4 + lc];
                mma_tf32(sacc[nf], a0, a1, a2, a3, b0, b1);
            }
        }

        // Scale + causal mask (register-resident).
        const bool needmask = (k0 + FBC - 1 > q0);
        const int r0g = q0 + wrow + lr;
        const int r1g = r0g + 8;
#pragma unroll
        for (int nf = 0; nf < 8; nf++) {
#pragma unroll
            for (int c = 0; c < 4; c++) {
                const int cg = k0 + nf * 8 + lc * 2 + (c & 1);
                float v = sacc[nf][c] * scale;
                if (needmask && cg > ((c & 2) ? r1g : r0g)) v = -1e9f;
                sacc[nf][c] = v;
            }
        }

        // Register softmax: row maxima via quad shfl.
        float tm0 = -1e30f, tm1 = -1e30f;
#pragma unroll
        for (int nf = 0; nf < 8; nf++) {
            tm0 = fmaxf(tm0, fmaxf(sacc[nf][0], sacc[nf][1]));
            tm1 = fmaxf(tm1, fmaxf(sacc[nf][2], sacc[nf][3]));
        }
        tm0 = fmaxf(tm0, __shfl_xor_sync(FULL, tm0, 1));
        tm0 = fmaxf(tm0, __shfl_xor_sync(FULL, tm0, 2));
        tm1 = fmaxf(tm1, __shfl_xor_sync(FULL, tm1, 1));
        tm1 = fmaxf(tm1, __shfl_xor_sync(FULL, tm1, 2));

        const float mn0 = fmaxf(m0, tm0);
        const float mn1 = fmaxf(m1, tm1);
        const float al0 = __expf(m0 - mn0);
        const float al1 = __expf(m1 - mn1);

        // Exponentiate in registers; keep probs as tf32 bits.
        uint32_t pb[8][4];
        float sum0 = 0.f, sum1 = 0.f;
#pragma unroll
        for (int nf = 0; nf < 8; nf++) {
            float p0 = __expf(sacc[nf][0] - mn0);
            float p1 = __expf(sacc[nf][1] - mn0);
            float p2 = __expf(sacc[nf][2] - mn1);
            float p3 = __expf(sacc[nf][3] - mn1);
            sum0 += p0 + p1;
            sum1 += p2 + p3;
            pb[nf][0] = f2tf32(p0); pb[nf][1] = f2tf32(p1);
            pb[nf][2] = f2tf32(p2); pb[nf][3] = f2tf32(p3);
        }
        sum0 += __shfl_xor_sync(FULL, sum0, 1);
        sum0 += __shfl_xor_sync(FULL, sum0, 2);
        sum1 += __shfl_xor_sync(FULL, sum1, 1);
        sum1 += __shfl_xor_sync(FULL, sum1, 2);
        l0 = l0 * al0 + sum0;
        l1 = l1 * al1 + sum1;
        m0 = mn0;
        m1 = mn1;

        // Rescale O.
#pragma unroll
        for (int nf = 0; nf < 16; nf++) {
            o[nf][0] *= al0; o[nf][1] *= al0;
            o[nf][2] *= al1; o[nf][3] *= al1;
        }

        // O += P @ V.  A-frags assembled from pb via quad shfls.
        const bool odd = (lc & 1);
#pragma unroll
        for (int ks = 0; ks < 8; ++ks) {
            uint32_t t00 = __shfl_sync(FULL, pb[ks][0], srcA);
            uint32_t t01 = __shfl_sync(FULL, pb[ks][1], srcA);
            uint32_t t10 = __shfl_sync(FULL, pb[ks][2], srcA);
            uint32_t t11 = __shfl_sync(FULL, pb[ks][3], srcA);
            uint32_t u00 = __shfl_sync(FULL, pb[ks][0], srcB);
            uint32_t u01 = __shfl_sync(FULL, pb[ks][1], srcB);
            uint32_t u10 = __shfl_sync(FULL, pb[ks][2], srcB);
            uint32_t u11 = __shfl_sync(FULL, pb[ks][3], srcB);
            uint32_t a0 = odd ? t01 : t00;
            uint32_t a1 = odd ? t11 : t10;
            uint32_t a2 = odd ? u01 : u00;
            uint32_t a3 = odd ? u11 : u10;
            const int k = ks * 8;
#pragma unroll
            for (int nf = 0; nf < 16; nf++) {
                const int n = nf * 8 + lr;
                uint32_t b0 = Vs[(k + lc) * QLD + n];
                uint32_t b1 = Vs[(k + 4 + lc) * QLD + n];
                mma_tf32(o[nf], a0, a1, a2, a3, b0, b1);
            }
        }
    }

    // Epilogue: normalize rows by 1/l and write ctx in (B,S,D).
    const int bb = bh / H_;
    const int hh = bh % H_;
    const float inv0 = 1.0f / l0;
    const float inv1 = 1.0f / l1;
    float* dst0 = ctx + ((size_t)bb * S_ + q0 + wrow + lr) * D_ + hh * HD_;
    float* dst1 = ctx + ((size_t)bb * S_ + q0 + wrow + lr + 8) * D_ + hh * HD_;
#pragma unroll
    for (int nf = 0; nf < 16; nf++) {
        const int cloc = nf * 8 + lc * 2;
        *reinterpret_cast<float2*>(dst0 + cloc) =
            make_float2(o[nf][0] * inv0, o[nf][1] * inv0);
        *reinterpret_cast<float2*>(dst1 + cloc) =
            make_float2(o[nf][2] * inv1, o[nf][3] * inv1);
    }
}

// ---------------------------------------------------------------------------
// kernel_launch
// ---------------------------------------------------------------------------
extern "C" void kernel_launch(void* const* d_in, const int* in_sizes, int n_in,
                              void* d_out, int out_size)
{
    const float* X  = (const float*)d_in[0];
    const float* Wq = (const float*)d_in[2];
    const float* bq = (const float*)d_in[3];
    const float* Wk = (const float*)d_in[4];
    const float* bk = (const float*)d_in[5];
    const float* Wv = (const float*)d_in[6];
    const float* bv = (const float*)d_in[7];
    const float* Wo = (const float*)d_in[8];
    const float* bo = (const float*)d_in[9];

    float* out = (float*)d_out;
    const size_t OFF = (size_t)B_ * S_ * D_;
    float* kout = out + OFF;
    float* vout = out + 2 * OFF;

    static float* qbuf = nullptr;
    static float* cbuf = nullptr;
    static const int FSMEM = (FBR * QLD + 2 * FBC * QLD) * (int)sizeof(uint32_t);
    if (qbuf == nullptr) {
        cudaGetSymbolAddress((void**)&qbuf, g_q);
        cudaGetSymbolAddress((void**)&cbuf, g_ctx);
        cudaFuncSetAttribute(flash_tc, cudaFuncAttributeMaxDynamicSharedMemorySize, FSMEM);
    }

    dim3 gg(D_ / BN, M_ / BM);   // (16, 32)
    gemm_tf32<<<gg, 256>>>(X, Wq, bq, qbuf, 1);
    gemm_tf32<<<gg, 256>>>(X, Wk, bk, kout, 1);
    gemm_tf32<<<gg, 256>>>(X, Wv, bv, vout, 1);

    flash_tc<<<dim3(S_ / FBR, B_ * H_), 256, FSMEM>>>(qbuf, kout, vout, cbuf);

    gemm_tf32<<<gg, 256>>>(cbuf, Wo, bo, out, 0);
}